// round 2
// baseline (speedup 1.0000x reference)
#include <cuda_runtime.h>
#include <cuda_bf16.h>
#include <math.h>

#define LL 1024
#define HH 2048
#define DI 4096
#define SN 16
#define RR 128

// ---------------- scratch (device globals; no allocations) ----------------
__device__ float g_hs_pre[LL * DI];
__device__ float g_gate[LL * DI];
__device__ float g_hs[LL * DI];
__device__ float g_ts[LL * RR];
__device__ float g_dt[LL * DI];
__device__ float g_Bm[LL * SN];
__device__ float g_Cm[LL * SN];
__device__ float g_y[LL * DI];

// ---------------- helpers ----------------
__device__ __forceinline__ float softplus_f(float v) {
    return v > 15.f ? v : log1pf(expf(v));
}
__device__ __forceinline__ float silu_f(float v) {
    return v / (1.f + __expf(-v));
}

// ---------------- generic tiled GEMM: C[M,N] = A[M,K] * B[N,K]^T -----------
// EPI = 0: plain store (or atomicAdd when gridDim.z > 1, i.e. split-K)
// EPI = 1: C = softplus(C + bias[n])
template <int BM, int BN, int BK, int TM, int TN, int EPI>
__global__ void gemm_nt(const float* __restrict__ A, const float* __restrict__ Bw,
                        float* __restrict__ C, int M, int Nn, int Kk,
                        const float* __restrict__ bias) {
    constexpr int NT = (BM / TM) * (BN / TN);
    __shared__ float As[BK][BM];
    __shared__ float Bs[BK][BN];

    const int tid  = threadIdx.x;
    const int tcol = tid % (BN / TN);
    const int trow = tid / (BN / TN);
    const int m0 = blockIdx.y * BM;
    const int n0 = blockIdx.x * BN;

    const int kPer = Kk / gridDim.z;
    const int kBeg = blockIdx.z * kPer;

    float acc[TM][TN];
#pragma unroll
    for (int i = 0; i < TM; i++)
#pragma unroll
        for (int j = 0; j < TN; j++) acc[i][j] = 0.f;

    for (int k0 = kBeg; k0 < kBeg + kPer; k0 += BK) {
        // load A tile (transposed into SMEM)
#pragma unroll
        for (int i = tid; i < BM * BK / 4; i += NT) {
            int row = i / (BK / 4);
            int kq  = i % (BK / 4);
            float4 v = *(const float4*)&A[(size_t)(m0 + row) * Kk + k0 + kq * 4];
            As[kq * 4 + 0][row] = v.x;
            As[kq * 4 + 1][row] = v.y;
            As[kq * 4 + 2][row] = v.z;
            As[kq * 4 + 3][row] = v.w;
        }
        // load B tile (transposed into SMEM)
#pragma unroll
        for (int i = tid; i < BN * BK / 4; i += NT) {
            int row = i / (BK / 4);
            int kq  = i % (BK / 4);
            float4 v = *(const float4*)&Bw[(size_t)(n0 + row) * Kk + k0 + kq * 4];
            Bs[kq * 4 + 0][row] = v.x;
            Bs[kq * 4 + 1][row] = v.y;
            Bs[kq * 4 + 2][row] = v.z;
            Bs[kq * 4 + 3][row] = v.w;
        }
        __syncthreads();

#pragma unroll
        for (int kk = 0; kk < BK; kk++) {
            float ar[TM], br[TN];
#pragma unroll
            for (int i = 0; i < TM; i++) ar[i] = As[kk][trow * TM + i];
#pragma unroll
            for (int j = 0; j < TN; j++) br[j] = Bs[kk][tcol * TN + j];
#pragma unroll
            for (int i = 0; i < TM; i++)
#pragma unroll
                for (int j = 0; j < TN; j++) acc[i][j] += ar[i] * br[j];
        }
        __syncthreads();
    }

    const bool splitk = (gridDim.z > 1);
#pragma unroll
    for (int i = 0; i < TM; i++) {
        int m = m0 + trow * TM + i;
#pragma unroll
        for (int j = 0; j < TN; j++) {
            int n = n0 + tcol * TN + j;
            float v = acc[i][j];
            if (splitk) {
                atomicAdd(&C[(size_t)m * Nn + n], v);
            } else {
                if (EPI == 1) v = softplus_f(v + bias[n]);
                C[(size_t)m * Nn + n] = v;
            }
        }
    }
}

// ---------------- zero fill ----------------
__global__ void zero_kernel(float* __restrict__ p, int n) {
    int i = blockIdx.x * blockDim.x + threadIdx.x;
    if (i < n) p[i] = 0.f;
}

// ---------------- causal depthwise conv (K=4) + silu ----------------
__global__ void conv_silu_kernel(const float* __restrict__ hs_pre,
                                 const float* __restrict__ cw,
                                 const float* __restrict__ cb,
                                 float* __restrict__ hs) {
    int idx = blockIdx.x * blockDim.x + threadIdx.x;  // over LL*DI
    int l = idx / DI;
    int d = idx % DI;
    float acc = cb[d];
#pragma unroll
    for (int j = 0; j < 4; j++) {
        int ll = l + j - 3;
        if (ll >= 0) acc += cw[d * 4 + j] * hs_pre[(size_t)ll * DI + d];
    }
    hs[idx] = silu_f(acc);
}

// ---------------- B/C projections: N=16 outputs each, warp-per-output -----
__global__ void bc_proj_kernel(const float* __restrict__ hs,
                               const float* __restrict__ Wb,
                               const float* __restrict__ Wc,
                               float* __restrict__ Bm, float* __restrict__ Cm) {
    int l = blockIdx.x;
    int w = threadIdx.x >> 5;
    int lane = threadIdx.x & 31;
    const float* W = (w < SN) ? (Wb + (size_t)w * DI) : (Wc + (size_t)(w - SN) * DI);
    const float4* h4 = (const float4*)(hs + (size_t)l * DI);
    const float4* W4 = (const float4*)W;
    float acc = 0.f;
#pragma unroll 4
    for (int i = lane; i < DI / 4; i += 32) {
        float4 a = h4[i];
        float4 b = W4[i];
        acc += a.x * b.x + a.y * b.y + a.z * b.z + a.w * b.w;
    }
#pragma unroll
    for (int m = 16; m > 0; m >>= 1) acc += __shfl_xor_sync(0xffffffffu, acc, m);
    if (lane == 0) {
        if (w < SN) Bm[l * SN + w] = acc;
        else        Cm[l * SN + (w - SN)] = acc;
    }
}

// ---------------- selective scan ----------------
// Block = 256 threads = 16 channels (dg) x 16 states (n). Grid = DI/16 = 256.
// 64-row SMEM staging for coalesced dt/hs/gate/y traffic; shfl-reduce over n.
#define CH 64
__global__ void scan_kernel(const float* __restrict__ dt, const float* __restrict__ hs,
                            const float* __restrict__ gate,
                            const float* __restrict__ Bm, const float* __restrict__ Cm,
                            const float* __restrict__ A_log, const float* __restrict__ Dp,
                            float* __restrict__ y) {
    __shared__ float s_dt[CH][SN], s_hs[CH][SN], s_gate[CH][SN];
    __shared__ float s_B[CH][SN], s_C[CH][SN], s_y[CH][SN];

    const int tid = threadIdx.x;
    const int n  = tid & 15;
    const int dg = tid >> 4;
    const int d0 = blockIdx.x * SN;
    const int d  = d0 + dg;

    const float Acoef = -expf(A_log[d * SN + n]);
    const float Dv = Dp[d];

    const int r = tid >> 2;      // staging row 0..63
    const int q = tid & 3;       // staging quad 0..3

    float state = 0.f;
    for (int l0 = 0; l0 < LL; l0 += CH) {
        // cooperative stage: one float4 per thread per array
        *(float4*)&s_dt[r][q * 4]   = *(const float4*)&dt[(size_t)(l0 + r) * DI + d0 + q * 4];
        *(float4*)&s_hs[r][q * 4]   = *(const float4*)&hs[(size_t)(l0 + r) * DI + d0 + q * 4];
        *(float4*)&s_gate[r][q * 4] = *(const float4*)&gate[(size_t)(l0 + r) * DI + d0 + q * 4];
        *(float4*)&s_B[r][q * 4]    = *(const float4*)&Bm[(l0 + r) * SN + q * 4];
        *(float4*)&s_C[r][q * 4]    = *(const float4*)&Cm[(l0 + r) * SN + q * 4];
        __syncthreads();

        for (int li = 0; li < CH; li++) {
            float dtv = s_dt[li][dg];
            float hsv = s_hs[li][dg];
            float bv  = s_B[li][n];
            float cv  = s_C[li][n];
            state = __expf(Acoef * dtv) * state + dtv * bv * hsv;
            float p = state * cv;
            p += __shfl_xor_sync(0xffffffffu, p, 1);
            p += __shfl_xor_sync(0xffffffffu, p, 2);
            p += __shfl_xor_sync(0xffffffffu, p, 4);
            p += __shfl_xor_sync(0xffffffffu, p, 8);
            if (n == 0) {
                float g = s_gate[li][dg];
                s_y[li][dg] = (p + hsv * Dv) * silu_f(g);
            }
        }
        __syncthreads();
        *(float4*)&y[(size_t)(l0 + r) * DI + d0 + q * 4] = *(const float4*)&s_y[r][q * 4];
        __syncthreads();
    }
}

// ---------------- launch ----------------
extern "C" void kernel_launch(void* const* d_in, const int* in_sizes, int n_in,
                              void* d_out, int out_size) {
    (void)in_sizes; (void)n_in; (void)out_size;
    const float* x        = (const float*)d_in[0];   // [1,L,H]
    const float* Wis      = (const float*)d_in[1];   // [DI,H]
    const float* Wig      = (const float*)d_in[2];   // [DI,H]
    const float* convw    = (const float*)d_in[3];   // [DI,4]
    const float* convb    = (const float*)d_in[4];   // [DI]
    const float* Wdt      = (const float*)d_in[5];   // [R,DI]
    const float* Wb       = (const float*)d_in[6];   // [N,DI]
    const float* Wc       = (const float*)d_in[7];   // [N,DI]
    const float* Wdtproj  = (const float*)d_in[8];   // [DI,R]
    const float* bdtproj  = (const float*)d_in[9];   // [DI]
    const float* A_log    = (const float*)d_in[10];  // [DI,N]
    const float* Dv       = (const float*)d_in[11];  // [DI]
    const float* Wout     = (const float*)d_in[12];  // [H,DI]
    float* out = (float*)d_out;                      // [1,L,H]

    float *hs_pre, *gate, *hs, *ts, *dtb, *Bm, *Cm, *y;
    cudaGetSymbolAddress((void**)&hs_pre, g_hs_pre);
    cudaGetSymbolAddress((void**)&gate,   g_gate);
    cudaGetSymbolAddress((void**)&hs,     g_hs);
    cudaGetSymbolAddress((void**)&ts,     g_ts);
    cudaGetSymbolAddress((void**)&dtb,    g_dt);
    cudaGetSymbolAddress((void**)&Bm,     g_Bm);
    cudaGetSymbolAddress((void**)&Cm,     g_Cm);
    cudaGetSymbolAddress((void**)&y,      g_y);

    // 1-2) input projections: [L,H] x [DI,H]^T -> [L,DI]
    gemm_nt<128, 128, 32, 8, 8, 0><<<dim3(DI / 128, LL / 128, 1), 256>>>(
        x, Wis, hs_pre, LL, DI, HH, nullptr);
    gemm_nt<128, 128, 32, 8, 8, 0><<<dim3(DI / 128, LL / 128, 1), 256>>>(
        x, Wig, gate, LL, DI, HH, nullptr);

    // 3) causal conv + silu -> hs [L,DI]
    conv_silu_kernel<<<(LL * DI) / 256, 256>>>(hs_pre, convw, convb, hs);

    // 4) time_step: [L,DI] x [R,DI]^T -> [L,R], 8-way split-K (N too small otherwise)
    zero_kernel<<<(LL * RR + 255) / 256, 256>>>(ts, LL * RR);
    gemm_nt<128, 128, 32, 8, 8, 0><<<dim3(1, LL / 128, 8), 256>>>(
        hs, Wdt, ts, LL, RR, DI, nullptr);

    // 5) dt = softplus(ts x Wdtproj^T + b) -> [L,DI]
    gemm_nt<128, 128, 32, 8, 8, 1><<<dim3(DI / 128, LL / 128, 1), 256>>>(
        ts, Wdtproj, dtb, LL, DI, RR, bdtproj);

    // 6) B/C projections -> [L,16] each
    bc_proj_kernel<<<LL, 1024>>>(hs, Wb, Wc, Bm, Cm);

    // 7) selective scan + D skip + gate -> y [L,DI]
    scan_kernel<<<DI / SN, 256>>>(dtb, hs, gate, Bm, Cm, A_log, Dv, y);

    // 8) out projection: [L,DI] x [H,DI]^T -> [L,H]
    gemm_nt<64, 128, 32, 8, 8, 0><<<dim3(HH / 128, LL / 64, 1), 128>>>(
        y, Wout, out, LL, HH, DI, nullptr);
}

// round 3
// speedup vs baseline: 2.9765x; 2.9765x over previous
#include <cuda_runtime.h>
#include <cuda_bf16.h>
#include <math.h>
#include <stdint.h>

#define LL 1024
#define HH 2048
#define DI 4096
#define SN 16
#define RR 128

// ---------------- scratch (device globals; no allocations) ----------------
__device__ float g_hs_pre[LL * DI];
__device__ float g_gate[LL * DI];
__device__ float g_hs[LL * DI];
__device__ float g_ts[LL * RR];
__device__ float g_dt[LL * DI];
__device__ float g_Bm[LL * SN];
__device__ float g_Cm[LL * SN];
__device__ float g_y[LL * DI];

// ---------------- helpers ----------------
__device__ __forceinline__ float softplus_f(float v) {
    return v > 15.f ? v : log1pf(expf(v));
}
__device__ __forceinline__ float silu_f(float v) {
    return v / (1.f + __expf(-v));
}
__device__ __forceinline__ uint32_t f2tf(float f) {
    uint32_t u;
    asm("cvt.rna.tf32.f32 %0, %1;" : "=r"(u) : "f"(f));
    return u;
}
__device__ __forceinline__ void cpa16(void* s, const void* g) {
    uint32_t sa = (uint32_t)__cvta_generic_to_shared(s);
    asm volatile("cp.async.cg.shared.global [%0], [%1], 16;" :: "r"(sa), "l"(g));
}
__device__ __forceinline__ void mma_tf32(float c[4], const uint32_t a[4], const uint32_t b[2]) {
    asm volatile(
        "mma.sync.aligned.m16n8k8.row.col.f32.tf32.tf32.f32 "
        "{%0,%1,%2,%3}, {%4,%5,%6,%7}, {%8,%9}, {%0,%1,%2,%3};"
        : "+f"(c[0]), "+f"(c[1]), "+f"(c[2]), "+f"(c[3])
        : "r"(a[0]), "r"(a[1]), "r"(a[2]), "r"(a[3]), "r"(b[0]), "r"(b[1]));
}

// ============ tf32 tensor-core GEMM: C[M,N] = A[M,K] * B[N,K]^T ============
// Tile 128x128xBK16, 256 threads (8 warps, 2x4), per-warp 64x32.
// cp.async double-buffered. SMEM row-major [row][k] with stride 20 floats
// (20*g mod 32 covers all multiples of 4 -> conflict-free fragment loads).
// gridDim.z > 1 => split-K with fp32 atomicAdd (C must be pre-zeroed).
// EPI==1 (non-splitK only): C = softplus(C + bias[n]).
#define BKP 20

__device__ __forceinline__ void tf32_load_stage(
    float (*as)[BKP], float (*bs)[BKP],
    const float* __restrict__ A, const float* __restrict__ Bw,
    int m0, int n0, int k0, int Kk, int tid) {
#pragma unroll
    for (int c = tid; c < 512; c += 256) {
        int row = c >> 2;
        int col = (c & 3) << 2;
        cpa16(&as[row][col], A + (size_t)(m0 + row) * Kk + k0 + col);
        cpa16(&bs[row][col], Bw + (size_t)(n0 + row) * Kk + k0 + col);
    }
}

template <int EPI>
__global__ void __launch_bounds__(256, 2)
gemm_tf32(const float* __restrict__ A, const float* __restrict__ Bw,
          float* __restrict__ C, int M, int Nn, int Kk,
          const float* __restrict__ bias) {
    __shared__ float As[2][128][BKP];
    __shared__ float Bs[2][128][BKP];

    const int tid  = threadIdx.x;
    const int lane = tid & 31;
    const int wid  = tid >> 5;
    const int wm = (wid >> 2) * 64;   // warp m-offset (0/64)
    const int wn = (wid & 3) * 32;    // warp n-offset (0/32/64/96)
    const int g = lane >> 2;          // group id 0..7
    const int t = lane & 3;           // thread-in-group 0..3

    const int m0 = blockIdx.y * 128;
    const int n0 = blockIdx.x * 128;
    const int kPer = Kk / gridDim.z;
    const int kBeg = blockIdx.z * kPer;

    float acc[4][4][4];
#pragma unroll
    for (int mt = 0; mt < 4; mt++)
#pragma unroll
        for (int nt = 0; nt < 4; nt++)
#pragma unroll
            for (int e = 0; e < 4; e++) acc[mt][nt][e] = 0.f;

    const int T = kPer / 16;
    tf32_load_stage(As[0], Bs[0], A, Bw, m0, n0, kBeg, Kk, tid);
    asm volatile("cp.async.commit_group;");

    int buf = 0;
    for (int it = 0; it < T; it++) {
        if (it + 1 < T) {
            tf32_load_stage(As[buf ^ 1], Bs[buf ^ 1], A, Bw, m0, n0,
                            kBeg + (it + 1) * 16, Kk, tid);
            asm volatile("cp.async.commit_group;");
            asm volatile("cp.async.wait_group 1;");
        } else {
            asm volatile("cp.async.wait_group 0;");
        }
        __syncthreads();

#pragma unroll
        for (int ks = 0; ks < 2; ks++) {
            const int kb = ks * 8;
            uint32_t af[4][4], bf[4][2];
#pragma unroll
            for (int mt = 0; mt < 4; mt++) {
                int r = wm + mt * 16 + g;
                af[mt][0] = f2tf(As[buf][r][kb + t]);
                af[mt][1] = f2tf(As[buf][r + 8][kb + t]);
                af[mt][2] = f2tf(As[buf][r][kb + t + 4]);
                af[mt][3] = f2tf(As[buf][r + 8][kb + t + 4]);
            }
#pragma unroll
            for (int nt = 0; nt < 4; nt++) {
                int rn = wn + nt * 8 + g;
                bf[nt][0] = f2tf(Bs[buf][rn][kb + t]);
                bf[nt][1] = f2tf(Bs[buf][rn][kb + t + 4]);
            }
#pragma unroll
            for (int mt = 0; mt < 4; mt++)
#pragma unroll
                for (int nt = 0; nt < 4; nt++)
                    mma_tf32(acc[mt][nt], af[mt], bf[nt]);
        }
        __syncthreads();
        buf ^= 1;
    }

    const bool splitk = (gridDim.z > 1);
#pragma unroll
    for (int mt = 0; mt < 4; mt++) {
#pragma unroll
        for (int nt = 0; nt < 4; nt++) {
            int m = m0 + wm + mt * 16 + g;
            int n = n0 + wn + nt * 8 + 2 * t;
            float* p0 = &C[(size_t)m * Nn + n];
            float* p1 = &C[(size_t)(m + 8) * Nn + n];
            if (splitk) {
                atomicAdd(p0 + 0, acc[mt][nt][0]);
                atomicAdd(p0 + 1, acc[mt][nt][1]);
                atomicAdd(p1 + 0, acc[mt][nt][2]);
                atomicAdd(p1 + 1, acc[mt][nt][3]);
            } else if (EPI == 1) {
                float b0 = bias[n], b1 = bias[n + 1];
                p0[0] = softplus_f(acc[mt][nt][0] + b0);
                p0[1] = softplus_f(acc[mt][nt][1] + b1);
                p1[0] = softplus_f(acc[mt][nt][2] + b0);
                p1[1] = softplus_f(acc[mt][nt][3] + b1);
            } else {
                *(float2*)p0 = make_float2(acc[mt][nt][0], acc[mt][nt][1]);
                *(float2*)p1 = make_float2(acc[mt][nt][2], acc[mt][nt][3]);
            }
        }
    }
}

// ---------------- zero fill ----------------
__global__ void zero_kernel(float* __restrict__ p, int n) {
    int i = blockIdx.x * blockDim.x + threadIdx.x;
    if (i < n) p[i] = 0.f;
}

// ---------------- causal depthwise conv (K=4) + silu ----------------
__global__ void conv_silu_kernel(const float* __restrict__ hs_pre,
                                 const float* __restrict__ cw,
                                 const float* __restrict__ cb,
                                 float* __restrict__ hs) {
    int idx = blockIdx.x * blockDim.x + threadIdx.x;  // over LL*DI
    int l = idx / DI;
    int d = idx % DI;
    float acc = cb[d];
#pragma unroll
    for (int j = 0; j < 4; j++) {
        int ll = l + j - 3;
        if (ll >= 0) acc += cw[d * 4 + j] * hs_pre[(size_t)ll * DI + d];
    }
    hs[idx] = silu_f(acc);
}

// ---------------- B/C projections: N=16 outputs each, warp-per-output -----
__global__ void bc_proj_kernel(const float* __restrict__ hs,
                               const float* __restrict__ Wb,
                               const float* __restrict__ Wc,
                               float* __restrict__ Bm, float* __restrict__ Cm) {
    int l = blockIdx.x;
    int w = threadIdx.x >> 5;
    int lane = threadIdx.x & 31;
    const float* W = (w < SN) ? (Wb + (size_t)w * DI) : (Wc + (size_t)(w - SN) * DI);
    const float4* h4 = (const float4*)(hs + (size_t)l * DI);
    const float4* W4 = (const float4*)W;
    float acc = 0.f;
#pragma unroll 4
    for (int i = lane; i < DI / 4; i += 32) {
        float4 a = h4[i];
        float4 b = W4[i];
        acc += a.x * b.x + a.y * b.y + a.z * b.z + a.w * b.w;
    }
#pragma unroll
    for (int m = 16; m > 0; m >>= 1) acc += __shfl_xor_sync(0xffffffffu, acc, m);
    if (lane == 0) {
        if (w < SN) Bm[l * SN + w] = acc;
        else        Cm[l * SN + (w - SN)] = acc;
    }
}

// ---------------- selective scan ----------------
// Block = 256 threads = 16 channels (dg) x 16 states (n). Grid = DI/16 = 256.
#define CH 64
__global__ void scan_kernel(const float* __restrict__ dt, const float* __restrict__ hs,
                            const float* __restrict__ gate,
                            const float* __restrict__ Bm, const float* __restrict__ Cm,
                            const float* __restrict__ A_log, const float* __restrict__ Dp,
                            float* __restrict__ y) {
    __shared__ float s_dt[CH][SN], s_hs[CH][SN], s_gate[CH][SN];
    __shared__ float s_B[CH][SN], s_C[CH][SN], s_y[CH][SN];

    const int tid = threadIdx.x;
    const int n  = tid & 15;
    const int dg = tid >> 4;
    const int d0 = blockIdx.x * SN;
    const int d  = d0 + dg;

    const float Acoef = -expf(A_log[d * SN + n]);
    const float Dv = Dp[d];

    const int r = tid >> 2;
    const int q = tid & 3;

    float state = 0.f;
    for (int l0 = 0; l0 < LL; l0 += CH) {
        *(float4*)&s_dt[r][q * 4]   = *(const float4*)&dt[(size_t)(l0 + r) * DI + d0 + q * 4];
        *(float4*)&s_hs[r][q * 4]   = *(const float4*)&hs[(size_t)(l0 + r) * DI + d0 + q * 4];
        *(float4*)&s_gate[r][q * 4] = *(const float4*)&gate[(size_t)(l0 + r) * DI + d0 + q * 4];
        *(float4*)&s_B[r][q * 4]    = *(const float4*)&Bm[(l0 + r) * SN + q * 4];
        *(float4*)&s_C[r][q * 4]    = *(const float4*)&Cm[(l0 + r) * SN + q * 4];
        __syncthreads();

        for (int li = 0; li < CH; li++) {
            float dtv = s_dt[li][dg];
            float hsv = s_hs[li][dg];
            float bv  = s_B[li][n];
            float cv  = s_C[li][n];
            state = __expf(Acoef * dtv) * state + dtv * bv * hsv;
            float p = state * cv;
            p += __shfl_xor_sync(0xffffffffu, p, 1);
            p += __shfl_xor_sync(0xffffffffu, p, 2);
            p += __shfl_xor_sync(0xffffffffu, p, 4);
            p += __shfl_xor_sync(0xffffffffu, p, 8);
            if (n == 0) {
                float ga = s_gate[li][dg];
                s_y[li][dg] = (p + hsv * Dv) * silu_f(ga);
            }
        }
        __syncthreads();
        *(float4*)&y[(size_t)(l0 + r) * DI + d0 + q * 4] = *(const float4*)&s_y[r][q * 4];
        __syncthreads();
    }
}

// ---------------- launch ----------------
extern "C" void kernel_launch(void* const* d_in, const int* in_sizes, int n_in,
                              void* d_out, int out_size) {
    (void)in_sizes; (void)n_in; (void)out_size;
    const float* x        = (const float*)d_in[0];   // [1,L,H]
    const float* Wis      = (const float*)d_in[1];   // [DI,H]
    const float* Wig      = (const float*)d_in[2];   // [DI,H]
    const float* convw    = (const float*)d_in[3];   // [DI,4]
    const float* convb    = (const float*)d_in[4];   // [DI]
    const float* Wdt      = (const float*)d_in[5];   // [R,DI]
    const float* Wb       = (const float*)d_in[6];   // [N,DI]
    const float* Wc       = (const float*)d_in[7];   // [N,DI]
    const float* Wdtproj  = (const float*)d_in[8];   // [DI,R]
    const float* bdtproj  = (const float*)d_in[9];   // [DI]
    const float* A_log    = (const float*)d_in[10];  // [DI,N]
    const float* Dv       = (const float*)d_in[11];  // [DI]
    const float* Wout     = (const float*)d_in[12];  // [H,DI]
    float* out = (float*)d_out;                      // [1,L,H]

    float *hs_pre, *gate, *hs, *ts, *dtb, *Bm, *Cm, *y;
    cudaGetSymbolAddress((void**)&hs_pre, g_hs_pre);
    cudaGetSymbolAddress((void**)&gate,   g_gate);
    cudaGetSymbolAddress((void**)&hs,     g_hs);
    cudaGetSymbolAddress((void**)&ts,     g_ts);
    cudaGetSymbolAddress((void**)&dtb,    g_dt);
    cudaGetSymbolAddress((void**)&Bm,     g_Bm);
    cudaGetSymbolAddress((void**)&Cm,     g_Cm);
    cudaGetSymbolAddress((void**)&y,      g_y);

    // 1-2) input projections: [L,H] x [DI,H]^T -> [L,DI]   (tf32 TC)
    gemm_tf32<0><<<dim3(DI / 128, LL / 128, 1), 256>>>(x, Wis, hs_pre, LL, DI, HH, nullptr);
    gemm_tf32<0><<<dim3(DI / 128, LL / 128, 1), 256>>>(x, Wig, gate, LL, DI, HH, nullptr);

    // 3) causal conv + silu -> hs [L,DI]
    conv_silu_kernel<<<(LL * DI) / 256, 256>>>(hs_pre, convw, convb, hs);

    // 4) time_step: [L,DI] x [R,DI]^T -> [L,R]  (tf32 TC, 4-way split-K)
    zero_kernel<<<(LL * RR + 255) / 256, 256>>>(ts, LL * RR);
    gemm_tf32<0><<<dim3(1, LL / 128, 4), 256>>>(hs, Wdt, ts, LL, RR, DI, nullptr);

    // 5) dt = softplus(ts x Wdtproj^T + b) -> [L,DI]  (tf32 TC, fused epilogue)
    gemm_tf32<1><<<dim3(DI / 128, LL / 128, 1), 256>>>(ts, Wdtproj, dtb, LL, DI, RR, bdtproj);

    // 6) B/C projections -> [L,16] each
    bc_proj_kernel<<<LL, 1024>>>(hs, Wb, Wc, Bm, Cm);

    // 7) selective scan + D skip + gate -> y [L,DI]
    scan_kernel<<<DI / SN, 256>>>(dtb, hs, gate, Bm, Cm, A_log, Dv, y);

    // 8) out projection: [L,DI] x [H,DI]^T -> [L,H]  (tf32 TC)
    gemm_tf32<0><<<dim3(HH / 128, LL / 64 / 2, 1), 256>>>(y, Wout, out, LL, HH, DI, nullptr);
}

// round 5
// speedup vs baseline: 3.3712x; 1.1326x over previous
#include <cuda_runtime.h>
#include <cuda_bf16.h>
#include <math.h>
#include <stdint.h>

#define LL 1024
#define HH 2048
#define DI 4096
#define SN 16
#define RR 128

// ---------------- scratch (device globals; no allocations) ----------------
__device__ float g_hs_pre[LL * DI];
__device__ float g_gate[LL * DI];
__device__ float g_hs[LL * DI];
__device__ float g_ts[LL * RR];
__device__ float g_dt[LL * DI];
__device__ float g_Bm[LL * SN];
__device__ float g_Cm[LL * SN];
__device__ float g_y[LL * DI];

// ---------------- helpers ----------------
__device__ __forceinline__ float softplus_f(float v) {
    return v > 15.f ? v : log1pf(expf(v));
}
__device__ __forceinline__ float silu_f(float v) {
    return v / (1.f + __expf(-v));
}
__device__ __forceinline__ uint32_t f2tf(float f) {
    uint32_t u;
    asm("cvt.rna.tf32.f32 %0, %1;" : "=r"(u) : "f"(f));
    return u;
}
__device__ __forceinline__ void cpa16(void* s, const void* g) {
    uint32_t sa = (uint32_t)__cvta_generic_to_shared(s);
    asm volatile("cp.async.cg.shared.global [%0], [%1], 16;" :: "r"(sa), "l"(g));
}
__device__ __forceinline__ void mma_tf32(float c[4], const uint32_t a[4], const uint32_t b0, const uint32_t b1) {
    asm volatile(
        "mma.sync.aligned.m16n8k8.row.col.f32.tf32.tf32.f32 "
        "{%0,%1,%2,%3}, {%4,%5,%6,%7}, {%8,%9}, {%0,%1,%2,%3};"
        : "+f"(c[0]), "+f"(c[1]), "+f"(c[2]), "+f"(c[3])
        : "r"(a[0]), "r"(a[1]), "r"(a[2]), "r"(a[3]), "r"(b0), "r"(b1));
}
__device__ __forceinline__ void ldsm_x4(uint32_t r[4], uint32_t saddr) {
    asm volatile("ldmatrix.sync.aligned.m8n8.x4.shared.b16 {%0,%1,%2,%3}, [%4];"
        : "=r"(r[0]), "=r"(r[1]), "=r"(r[2]), "=r"(r[3]) : "r"(saddr));
}

// ================= FAT tf32 GEMM: C[M,N] = A[M,K] * B[N,K]^T ===============
// 128x128x16 tile, 128 threads (4 warps, 2x2), warp tile 64x64.
// SMEM holds PRE-CONVERTED tf32 (cvt done in staging). Fragments via ldmatrix.
// Stride-20 rows => conflict-free LDSM. Register-staged GMEM pipeline.
#define FKP 20

__global__ void __launch_bounds__(128, 2)
gemm_fat(const float* __restrict__ A, const float* __restrict__ Bw,
         float* __restrict__ C, int M, int Nn, int Kk) {
    __shared__ __align__(16) uint32_t As[128][FKP];
    __shared__ __align__(16) uint32_t Bs[128][FKP];

    const int tid  = threadIdx.x;
    const int lane = tid & 31;
    const int wid  = tid >> 5;
    const int wm = (wid >> 1) * 64;
    const int wn = (wid & 1) * 64;

    const int m0 = blockIdx.y * 128;
    const int n0 = blockIdx.x * 128;

    // ldmatrix per-lane base addresses (bytes into SMEM)
    uint32_t as_base = (uint32_t)__cvta_generic_to_shared(&As[0][0]);
    uint32_t bs_base = (uint32_t)__cvta_generic_to_shared(&Bs[0][0]);
    const int ra = wm + (lane & 15);
    const int ca = (lane >> 4) << 2;
    const uint32_t a_addr = as_base + ((ra * FKP + ca) << 2);
    const int rb = wn + ((lane >> 4) << 3) + (lane & 7);
    const int cb = ((lane >> 3) & 1) << 2;
    const uint32_t b_addr = bs_base + ((rb * FKP + cb) << 2);

    float acc[4][8][4];
#pragma unroll
    for (int mt = 0; mt < 4; mt++)
#pragma unroll
        for (int nt = 0; nt < 8; nt++)
#pragma unroll
            for (int e = 0; e < 4; e++) acc[mt][nt][e] = 0.f;

    // staging registers: 4 float4 per matrix per thread
    float4 ar[4], br[4];
    const int T = Kk / 16;

    // prologue load k-tile 0
#pragma unroll
    for (int i = 0; i < 4; i++) {
        int f = tid + (i << 7);
        int row = f >> 2, cq = (f & 3) << 2;
        ar[i] = *(const float4*)&A[(size_t)(m0 + row) * Kk + cq];
        br[i] = *(const float4*)&Bw[(size_t)(n0 + row) * Kk + cq];
    }

    for (int kt = 0; kt < T; kt++) {
        __syncthreads();
        // cvt + store staged tile
#pragma unroll
        for (int i = 0; i < 4; i++) {
            int f = tid + (i << 7);
            int row = f >> 2, cq = (f & 3) << 2;
            uint4 ua = make_uint4(f2tf(ar[i].x), f2tf(ar[i].y), f2tf(ar[i].z), f2tf(ar[i].w));
            uint4 ub = make_uint4(f2tf(br[i].x), f2tf(br[i].y), f2tf(br[i].z), f2tf(br[i].w));
            *(uint4*)&As[row][cq] = ua;
            *(uint4*)&Bs[row][cq] = ub;
        }
        __syncthreads();
        // prefetch next tile into regs (overlaps with compute below)
        if (kt + 1 < T) {
            int k0 = (kt + 1) * 16;
#pragma unroll
            for (int i = 0; i < 4; i++) {
                int f = tid + (i << 7);
                int row = f >> 2, cq = (f & 3) << 2;
                ar[i] = *(const float4*)&A[(size_t)(m0 + row) * Kk + k0 + cq];
                br[i] = *(const float4*)&Bw[(size_t)(n0 + row) * Kk + k0 + cq];
            }
        }
        // compute two k8 steps
#pragma unroll
        for (int ks = 0; ks < 2; ks++) {
            uint32_t af[4][4], bf[4][4];
#pragma unroll
            for (int mt = 0; mt < 4; mt++)
                ldsm_x4(af[mt], a_addr + mt * (16 * FKP * 4) + ks * 32);
#pragma unroll
            for (int np = 0; np < 4; np++)
                ldsm_x4(bf[np], b_addr + np * (16 * FKP * 4) + ks * 32);
#pragma unroll
            for (int mt = 0; mt < 4; mt++)
#pragma unroll
                for (int np = 0; np < 4; np++) {
                    mma_tf32(acc[mt][2 * np],     af[mt], bf[np][0], bf[np][1]);
                    mma_tf32(acc[mt][2 * np + 1], af[mt], bf[np][2], bf[np][3]);
                }
        }
    }

    const int g = lane >> 2;
    const int t = lane & 3;
#pragma unroll
    for (int mt = 0; mt < 4; mt++) {
#pragma unroll
        for (int nt = 0; nt < 8; nt++) {
            int m = m0 + wm + mt * 16 + g;
            int n = n0 + wn + nt * 8 + 2 * t;
            *(float2*)&C[(size_t)m * Nn + n]       = make_float2(acc[mt][nt][0], acc[mt][nt][1]);
            *(float2*)&C[(size_t)(m + 8) * Nn + n] = make_float2(acc[mt][nt][2], acc[mt][nt][3]);
        }
    }
}

// ============ small tf32 GEMM (R3 version): C = A * B^T ====================
// EPI==1: softplus(C+bias). gridDim.z>1: split-K atomicAdd.
#define BKP 20

__device__ __forceinline__ void tf32_load_stage(
    float (*as)[BKP], float (*bs)[BKP],
    const float* __restrict__ A, const float* __restrict__ Bw,
    int m0, int n0, int k0, int Kk, int tid) {
#pragma unroll
    for (int c = tid; c < 512; c += 256) {
        int row = c >> 2;
        int col = (c & 3) << 2;
        cpa16(&as[row][col], A + (size_t)(m0 + row) * Kk + k0 + col);
        cpa16(&bs[row][col], Bw + (size_t)(n0 + row) * Kk + k0 + col);
    }
}

template <int EPI>
__global__ void __launch_bounds__(256, 2)
gemm_tf32(const float* __restrict__ A, const float* __restrict__ Bw,
          float* __restrict__ C, int M, int Nn, int Kk,
          const float* __restrict__ bias) {
    __shared__ float As[2][128][BKP];
    __shared__ float Bs[2][128][BKP];

    const int tid  = threadIdx.x;
    const int lane = tid & 31;
    const int wid  = tid >> 5;
    const int wm = (wid >> 2) * 64;
    const int wn = (wid & 3) * 32;
    const int g = lane >> 2;
    const int t = lane & 3;

    const int m0 = blockIdx.y * 128;
    const int n0 = blockIdx.x * 128;
    const int kPer = Kk / gridDim.z;
    const int kBeg = blockIdx.z * kPer;

    float acc[4][4][4];
#pragma unroll
    for (int mt = 0; mt < 4; mt++)
#pragma unroll
        for (int nt = 0; nt < 4; nt++)
#pragma unroll
            for (int e = 0; e < 4; e++) acc[mt][nt][e] = 0.f;

    const int T = kPer / 16;
    tf32_load_stage(As[0], Bs[0], A, Bw, m0, n0, kBeg, Kk, tid);
    asm volatile("cp.async.commit_group;");

    int buf = 0;
    for (int it = 0; it < T; it++) {
        if (it + 1 < T) {
            tf32_load_stage(As[buf ^ 1], Bs[buf ^ 1], A, Bw, m0, n0,
                            kBeg + (it + 1) * 16, Kk, tid);
            asm volatile("cp.async.commit_group;");
            asm volatile("cp.async.wait_group 1;");
        } else {
            asm volatile("cp.async.wait_group 0;");
        }
        __syncthreads();

#pragma unroll
        for (int ks = 0; ks < 2; ks++) {
            const int kb = ks * 8;
            uint32_t af[4][4], bf[4][2];
#pragma unroll
            for (int mt = 0; mt < 4; mt++) {
                int r = wm + mt * 16 + g;
                af[mt][0] = f2tf(As[buf][r][kb + t]);
                af[mt][1] = f2tf(As[buf][r + 8][kb + t]);
                af[mt][2] = f2tf(As[buf][r][kb + t + 4]);
                af[mt][3] = f2tf(As[buf][r + 8][kb + t + 4]);
            }
#pragma unroll
            for (int nt = 0; nt < 4; nt++) {
                int rn = wn + nt * 8 + g;
                bf[nt][0] = f2tf(Bs[buf][rn][kb + t]);
                bf[nt][1] = f2tf(Bs[buf][rn][kb + t + 4]);
            }
#pragma unroll
            for (int mt = 0; mt < 4; mt++)
#pragma unroll
                for (int nt = 0; nt < 4; nt++)
                    mma_tf32(acc[mt][nt], af[mt], bf[nt][0], bf[nt][1]);
        }
        __syncthreads();
        buf ^= 1;
    }

    const bool splitk = (gridDim.z > 1);
#pragma unroll
    for (int mt = 0; mt < 4; mt++) {
#pragma unroll
        for (int nt = 0; nt < 4; nt++) {
            int m = m0 + wm + mt * 16 + g;
            int n = n0 + wn + nt * 8 + 2 * t;
            float* p0 = &C[(size_t)m * Nn + n];
            float* p1 = &C[(size_t)(m + 8) * Nn + n];
            if (splitk) {
                atomicAdd(p0 + 0, acc[mt][nt][0]);
                atomicAdd(p0 + 1, acc[mt][nt][1]);
                atomicAdd(p1 + 0, acc[mt][nt][2]);
                atomicAdd(p1 + 1, acc[mt][nt][3]);
            } else if (EPI == 1) {
                float b0 = bias[n], b1 = bias[n + 1];
                p0[0] = softplus_f(acc[mt][nt][0] + b0);
                p0[1] = softplus_f(acc[mt][nt][1] + b1);
                p1[0] = softplus_f(acc[mt][nt][2] + b0);
                p1[1] = softplus_f(acc[mt][nt][3] + b1);
            } else {
                *(float2*)p0 = make_float2(acc[mt][nt][0], acc[mt][nt][1]);
                *(float2*)p1 = make_float2(acc[mt][nt][2], acc[mt][nt][3]);
            }
        }
    }
}

// ---------------- zero fill ----------------
__global__ void zero_kernel(float* __restrict__ p, int n) {
    int i = blockIdx.x * blockDim.x + threadIdx.x;
    if (i < n) p[i] = 0.f;
}

// ---------------- causal depthwise conv (K=4) + silu ----------------
__global__ void conv_silu_kernel(const float* __restrict__ hs_pre,
                                 const float* __restrict__ cw,
                                 const float* __restrict__ cb,
                                 float* __restrict__ hs) {
    int idx = blockIdx.x * blockDim.x + threadIdx.x;
    int l = idx / DI;
    int d = idx % DI;
    float acc = cb[d];
#pragma unroll
    for (int j = 0; j < 4; j++) {
        int ll = l + j - 3;
        if (ll >= 0) acc += cw[d * 4 + j] * hs_pre[(size_t)ll * DI + d];
    }
    hs[idx] = silu_f(acc);
}

// ---------------- B/C projections ----------------
__global__ void bc_proj_kernel(const float* __restrict__ hs,
                               const float* __restrict__ Wb,
                               const float* __restrict__ Wc,
                               float* __restrict__ Bm, float* __restrict__ Cm) {
    int l = blockIdx.x;
    int w = threadIdx.x >> 5;
    int lane = threadIdx.x & 31;
    const float* W = (w < SN) ? (Wb + (size_t)w * DI) : (Wc + (size_t)(w - SN) * DI);
    const float4* h4 = (const float4*)(hs + (size_t)l * DI);
    const float4* W4 = (const float4*)W;
    float acc = 0.f;
#pragma unroll 4
    for (int i = lane; i < DI / 4; i += 32) {
        float4 a = h4[i];
        float4 b = W4[i];
        acc += a.x * b.x + a.y * b.y + a.z * b.z + a.w * b.w;
    }
#pragma unroll
    for (int m = 16; m > 0; m >>= 1) acc += __shfl_xor_sync(0xffffffffu, acc, m);
    if (lane == 0) {
        if (w < SN) Bm[l * SN + w] = acc;
        else        Cm[l * SN + (w - SN)] = acc;
    }
}

// ---------------- selective scan v2 (batched butterfly) ----------------
#define CH 64
__global__ void scan_kernel(const float* __restrict__ dt, const float* __restrict__ hs,
                            const float* __restrict__ gate,
                            const float* __restrict__ Bm, const float* __restrict__ Cm,
                            const float* __restrict__ A_log, const float* __restrict__ Dp,
                            float* __restrict__ y) {
    __shared__ float s_dt[CH][SN], s_hs[CH][SN], s_gate[CH][SN];
    __shared__ float s_B[CH][SN], s_C[CH][SN], s_y[CH][SN];

    const int tid = threadIdx.x;
    const int n  = tid & 15;
    const int dg = tid >> 4;
    const int d0 = blockIdx.x * SN;
    const int d  = d0 + dg;

    const float Acoef = -expf(A_log[d * SN + n]);
    const float Dv = Dp[d];

    const int r = tid >> 2;
    const int q = tid & 3;

    float state = 0.f;
    for (int l0 = 0; l0 < LL; l0 += CH) {
        *(float4*)&s_dt[r][q * 4]   = *(const float4*)&dt[(size_t)(l0 + r) * DI + d0 + q * 4];
        *(float4*)&s_hs[r][q * 4]   = *(const float4*)&hs[(size_t)(l0 + r) * DI + d0 + q * 4];
        *(float4*)&s_gate[r][q * 4] = *(const float4*)&gate[(size_t)(l0 + r) * DI + d0 + q * 4];
        *(float4*)&s_B[r][q * 4]    = *(const float4*)&Bm[(l0 + r) * SN + q * 4];
        *(float4*)&s_C[r][q * 4]    = *(const float4*)&Cm[(l0 + r) * SN + q * 4];
        __syncthreads();

        for (int lc = 0; lc < CH; lc += 8) {
            float p[8];
#pragma unroll
            for (int j = 0; j < 8; j++) {
                int li = lc + j;
                float dtv = s_dt[li][dg];
                float hsv = s_hs[li][dg];
                float dBu = dtv * s_B[li][n] * hsv;
                state = __expf(Acoef * dtv) * state + dBu;
                p[j] = state * s_C[li][n];
            }
#pragma unroll
            for (int m = 1; m < 16; m <<= 1) {
#pragma unroll
                for (int j = 0; j < 8; j++) p[j] += __shfl_xor_sync(0xffffffffu, p[j], m);
            }
            if (n == 0) {
#pragma unroll
                for (int j = 0; j < 8; j++) {
                    int li = lc + j;
                    s_y[li][dg] = (p[j] + s_hs[li][dg] * Dv) * silu_f(s_gate[li][dg]);
                }
            }
        }
        __syncthreads();
        *(float4*)&y[(size_t)(l0 + r) * DI + d0 + q * 4] = *(const float4*)&s_y[r][q * 4];
        __syncthreads();
    }
}

// ---------------- launch ----------------
extern "C" void kernel_launch(void* const* d_in, const int* in_sizes, int n_in,
                              void* d_out, int out_size) {
    (void)in_sizes; (void)n_in; (void)out_size;
    const float* x        = (const float*)d_in[0];
    const float* Wis      = (const float*)d_in[1];
    const float* Wig      = (const float*)d_in[2];
    const float* convw    = (const float*)d_in[3];
    const float* convb    = (const float*)d_in[4];
    const float* Wdt      = (const float*)d_in[5];
    const float* Wb       = (const float*)d_in[6];
    const float* Wc       = (const float*)d_in[7];
    const float* Wdtproj  = (const float*)d_in[8];
    const float* bdtproj  = (const float*)d_in[9];
    const float* A_log    = (const float*)d_in[10];
    const float* Dv       = (const float*)d_in[11];
    const float* Wout     = (const float*)d_in[12];
    float* out = (float*)d_out;

    float *hs_pre, *gate, *hs, *ts, *dtb, *Bm, *Cm, *y;
    cudaGetSymbolAddress((void**)&hs_pre, g_hs_pre);
    cudaGetSymbolAddress((void**)&gate,   g_gate);
    cudaGetSymbolAddress((void**)&hs,     g_hs);
    cudaGetSymbolAddress((void**)&ts,     g_ts);
    cudaGetSymbolAddress((void**)&dtb,    g_dt);
    cudaGetSymbolAddress((void**)&Bm,     g_Bm);
    cudaGetSymbolAddress((void**)&Cm,     g_Cm);
    cudaGetSymbolAddress((void**)&y,      g_y);

    // 1-2) input projections (fat tf32 TC)
    gemm_fat<<<dim3(DI / 128, LL / 128), 128>>>(x, Wis, hs_pre, LL, DI, HH);
    gemm_fat<<<dim3(DI / 128, LL / 128), 128>>>(x, Wig, gate, LL, DI, HH);

    // 3) causal conv + silu
    conv_silu_kernel<<<(LL * DI) / 256, 256>>>(hs_pre, convw, convb, hs);

    // 4) time_step (small tf32, 4-way split-K)
    zero_kernel<<<(LL * RR + 255) / 256, 256>>>(ts, LL * RR);
    gemm_tf32<0><<<dim3(1, LL / 128, 4), 256>>>(hs, Wdt, ts, LL, RR, DI, nullptr);

    // 5) dt = softplus(ts x Wdtproj^T + b)
    gemm_tf32<1><<<dim3(DI / 128, LL / 128, 1), 256>>>(ts, Wdtproj, dtb, LL, DI, RR, bdtproj);

    // 6) B/C projections
    bc_proj_kernel<<<LL, 1024>>>(hs, Wb, Wc, Bm, Cm);

    // 7) selective scan
    scan_kernel<<<DI / SN, 256>>>(dtb, hs, gate, Bm, Cm, A_log, Dv, y);

    // 8) out projection (fat tf32 TC)
    gemm_fat<<<dim3(HH / 128, LL / 128), 128>>>(y, Wout, out, LL, HH, DI);
}